// round 3
// baseline (speedup 1.0000x reference)
#include <cuda_runtime.h>
#include <cstdint>

#define N_DIM   512
#define K_DIM   32768
#define L_DIM   64
#define KTILE   128
#define NCHUNK  32
#define NCHUNKS (N_DIM / NCHUNK)     // 16
#define TOUT    1048608              // (32768-1)*32 + 64

#define CS_PITCH 132                 // conflict-free A-fragment reads
#define VS_PITCH 72                  // conflict-free B-fragment reads
#define CS_SZ    (NCHUNK * CS_PITCH) // 4224 floats per buffer
#define VS_OFF   (2 * CS_SZ)         // 8448
#define SMEM_FLOATS (VS_OFF + NCHUNK * VS_PITCH)  // 10752 floats = 43008 B
#define FR_PITCH 66                  // epilogue frame staging (128 x 66 = 8448 <= reuse)

static __device__ __forceinline__ uint32_t f2tf32(float f) {
    uint32_t u;
    asm("cvt.rna.tf32.f32 %0, %1;" : "=r"(u) : "f"(f));
    return u;
}

static __device__ __forceinline__ void mma_tf32(float d[4], const uint32_t a[4],
                                                const uint32_t b[2]) {
    asm volatile(
        "mma.sync.aligned.m16n8k8.row.col.f32.tf32.tf32.f32 "
        "{%0,%1,%2,%3}, {%4,%5,%6,%7}, {%8,%9}, {%0,%1,%2,%3};"
        : "+f"(d[0]), "+f"(d[1]), "+f"(d[2]), "+f"(d[3])
        : "r"(a[0]), "r"(a[1]), "r"(a[2]), "r"(a[3]), "r"(b[0]), "r"(b[1]));
}

__global__ void zero_kernel(float4* __restrict__ y, int n4) {
    int i = blockIdx.x * blockDim.x + threadIdx.x;
    if (i < n4) y[i] = make_float4(0.f, 0.f, 0.f, 0.f);
}

__global__ void __launch_bounds__(256)
decoder_kernel(const float* __restrict__ c, const float* __restrict__ V,
               float* __restrict__ y) {
    __shared__ __align__(16) float sm[SMEM_FLOATS];

    const int tid  = threadIdx.x;
    const int wid  = tid >> 5;
    const int lane = tid & 31;
    const int grp  = lane >> 2;        // 0..7
    const int qid  = lane & 3;         // 0..3
    const int k0   = blockIdx.x * KTILE;
    const int b    = blockIdx.y;
    const int wm   = (wid & 3) * 32;   // warp m-offset (k-frames)
    const int wn   = (wid >> 2) * 32;  // warp n-offset (l)

    const float* cb = c + ((size_t)b * N_DIM) * K_DIM + k0;

    float acc[2][4][4];
    #pragma unroll
    for (int mt = 0; mt < 2; ++mt)
        #pragma unroll
        for (int bt = 0; bt < 4; ++bt)
            #pragma unroll
            for (int r = 0; r < 4; ++r) acc[mt][bt][r] = 0.f;

    uint32_t creg[16], vreg[8];

    // ---- stage chunk 0 ----
    {
        const int n0 = 0;
        #pragma unroll
        for (int it = 0; it < 4; ++it) {
            const int idx = it * 256 + tid;
            const int n = idx >> 5, q = idx & 31;
            float4 v = *reinterpret_cast<const float4*>(cb + (size_t)(n0 + n) * K_DIM + 4 * q);
            creg[it * 4 + 0] = f2tf32(v.x); creg[it * 4 + 1] = f2tf32(v.y);
            creg[it * 4 + 2] = f2tf32(v.z); creg[it * 4 + 3] = f2tf32(v.w);
        }
        #pragma unroll
        for (int it = 0; it < 8; ++it) {
            const int idx = it * 256 + tid;
            const int l = idx >> 5, n = idx & 31;
            vreg[it] = f2tf32(__ldg(V + l * N_DIM + n0 + n));
        }
        float* cs = sm;
        #pragma unroll
        for (int it = 0; it < 4; ++it) {
            const int idx = it * 256 + tid;
            const int n = idx >> 5, q = idx & 31;
            *reinterpret_cast<uint4*>(cs + n * CS_PITCH + 4 * q) =
                make_uint4(creg[it*4+0], creg[it*4+1], creg[it*4+2], creg[it*4+3]);
        }
        float* vs = sm + VS_OFF;
        #pragma unroll
        for (int it = 0; it < 8; ++it) {
            const int idx = it * 256 + tid;
            const int l = idx >> 5, n = idx & 31;
            reinterpret_cast<uint32_t*>(vs)[n * VS_PITCH + l] = vreg[it];
        }
    }
    __syncthreads();

    #pragma unroll 1
    for (int cc = 0; cc < NCHUNKS; ++cc) {
        // ---- prefetch next chunk into registers (hidden behind MMA) ----
        if (cc + 1 < NCHUNKS) {
            const int n0 = (cc + 1) * NCHUNK;
            #pragma unroll
            for (int it = 0; it < 4; ++it) {
                const int idx = it * 256 + tid;
                const int n = idx >> 5, q = idx & 31;
                float4 v = *reinterpret_cast<const float4*>(cb + (size_t)(n0 + n) * K_DIM + 4 * q);
                creg[it * 4 + 0] = f2tf32(v.x); creg[it * 4 + 1] = f2tf32(v.y);
                creg[it * 4 + 2] = f2tf32(v.z); creg[it * 4 + 3] = f2tf32(v.w);
            }
            #pragma unroll
            for (int it = 0; it < 8; ++it) {
                const int idx = it * 256 + tid;
                const int l = idx >> 5, n = idx & 31;
                vreg[it] = f2tf32(__ldg(V + l * N_DIM + n0 + n));
            }
        }

        // ---- compute on current buffer ----
        {
            const float* cs = sm + (cc & 1) * CS_SZ;
            const float* vs = sm + VS_OFF;
            #pragma unroll
            for (int s = 0; s < 4; ++s) {
                uint32_t a[2][4], bf[4][2];
                const uint32_t* ar0 = reinterpret_cast<const uint32_t*>(
                    cs + (8 * s + qid) * CS_PITCH + wm + grp);
                const uint32_t* ar1 = reinterpret_cast<const uint32_t*>(
                    cs + (8 * s + qid + 4) * CS_PITCH + wm + grp);
                #pragma unroll
                for (int mt = 0; mt < 2; ++mt) {
                    a[mt][0] = ar0[mt * 16];
                    a[mt][1] = ar0[mt * 16 + 8];
                    a[mt][2] = ar1[mt * 16];
                    a[mt][3] = ar1[mt * 16 + 8];
                }
                const uint32_t* br0 = reinterpret_cast<const uint32_t*>(
                    vs + (8 * s + qid) * VS_PITCH + wn + grp);
                const uint32_t* br1 = reinterpret_cast<const uint32_t*>(
                    vs + (8 * s + qid + 4) * VS_PITCH + wn + grp);
                #pragma unroll
                for (int bt = 0; bt < 4; ++bt) {
                    bf[bt][0] = br0[bt * 8];
                    bf[bt][1] = br1[bt * 8];
                }
                #pragma unroll
                for (int mt = 0; mt < 2; ++mt)
                    #pragma unroll
                    for (int bt = 0; bt < 4; ++bt)
                        mma_tf32(acc[mt][bt], a[mt], bf[bt]);
            }
        }
        __syncthreads();

        // ---- store staged next chunk ----
        if (cc + 1 < NCHUNKS) {
            float* cs = sm + ((cc + 1) & 1) * CS_SZ;
            #pragma unroll
            for (int it = 0; it < 4; ++it) {
                const int idx = it * 256 + tid;
                const int n = idx >> 5, q = idx & 31;
                *reinterpret_cast<uint4*>(cs + n * CS_PITCH + 4 * q) =
                    make_uint4(creg[it*4+0], creg[it*4+1], creg[it*4+2], creg[it*4+3]);
            }
            float* vs = sm + VS_OFF;
            #pragma unroll
            for (int it = 0; it < 8; ++it) {
                const int idx = it * 256 + tid;
                const int n = idx & 31, l = idx >> 5;
                // note: staged with (l = idx>>5, n = idx&31) mapping
                reinterpret_cast<uint32_t*>(vs)[n * VS_PITCH + l] =
                    vreg[it];
            }
        }
        __syncthreads();
    }

    // ---- epilogue: frames -> SMEM (reuse buffers), overlap-add -> gmem ----
    float* fr = sm;   // 128 x FR_PITCH
    #pragma unroll
    for (int mt = 0; mt < 2; ++mt) {
        #pragma unroll
        for (int bt = 0; bt < 4; ++bt) {
            const int row = wm + mt * 16 + grp;
            const int col = wn + bt * 8 + 2 * qid;
            *reinterpret_cast<float2*>(fr + row * FR_PITCH + col) =
                make_float2(acc[mt][bt][0], acc[mt][bt][1]);
            *reinterpret_cast<float2*>(fr + (row + 8) * FR_PITCH + col) =
                make_float2(acc[mt][bt][2], acc[mt][bt][3]);
        }
    }
    __syncthreads();

    float* yb = y + (size_t)b * TOUT;
    if (tid < 128) {
        const int k = tid;
        if (k == 0) {
            #pragma unroll
            for (int j = 0; j < 32; ++j)
                atomicAdd(&yb[(size_t)32 * k0 + j], fr[j]);
        } else {
            const float* f0 = fr + k * FR_PITCH;
            const float* f1 = fr + (k - 1) * FR_PITCH + 32;
            float4* o = reinterpret_cast<float4*>(yb + (size_t)32 * (k0 + k));
            #pragma unroll
            for (int q = 0; q < 8; ++q)
                o[q] = make_float4(f0[4*q+0] + f1[4*q+0], f0[4*q+1] + f1[4*q+1],
                                   f0[4*q+2] + f1[4*q+2], f0[4*q+3] + f1[4*q+3]);
        }
        if (k == 127) {
            const float* f1 = fr + 127 * FR_PITCH + 32;
            #pragma unroll
            for (int j = 0; j < 32; ++j)
                atomicAdd(&yb[(size_t)32 * (k0 + KTILE) + j], f1[j]);
        }
    }
}

extern "C" void kernel_launch(void* const* d_in, const int* in_sizes, int n_in,
                              void* d_out, int out_size) {
    // c is the big input, V the small one (defensive ordering)
    const float* c = (const float*)d_in[0];
    const float* V = (const float*)d_in[1];
    if (in_sizes[0] == L_DIM * N_DIM) { c = (const float*)d_in[1]; V = (const float*)d_in[0]; }
    float* y = (float*)d_out;

    const int n4 = out_size / 4;
    zero_kernel<<<(n4 + 255) / 256, 256>>>((float4*)y, n4);

    dim3 grid(K_DIM / KTILE, 8);   // (256, 8)
    decoder_kernel<<<grid, 256>>>(c, V, y);
}